// round 13
// baseline (speedup 1.0000x reference)
#include <cuda_runtime.h>
#include <cuda_bf16.h>

// Inputs (metadata order):
//   d_in[0] : energy_readout            float32 [262144]
//   d_in[1] : atomic_numbers            int32   [8388608]
//   d_in[2] : atomic_subsystem_indices  int32   [8388608]  (sorted ascending)
//   d_in[3] : self_energies_tensor      float32 [100]
// Output: float32 [262144] = energy_readout + segment_sum(se[Z], seg_idx)

#define LUT_SIZE_MAX 128
#define CHUNK 4           // atoms per thread (exactly one chunk per thread)
#define TPB 256

__global__ void init_out_kernel(const float* __restrict__ e,
                                float* __restrict__ out, int n4) {
    int i = blockIdx.x * blockDim.x + threadIdx.x;
    if (i < n4) {
        reinterpret_cast<float4*>(out)[i] =
            reinterpret_cast<const float4*>(e)[i];
    }
}

__global__ void __launch_bounds__(TPB, 8)
self_energy_segsum_kernel(const int* __restrict__ zs,
                          const int* __restrict__ seg,
                          const float* __restrict__ se,
                          float* __restrict__ out,
                          int n_atoms, int n_se) {
    __shared__ float s_se[LUT_SIZE_MAX];
    for (int i = threadIdx.x; i < LUT_SIZE_MAX; i += blockDim.x)
        s_se[i] = (i < n_se) ? se[i] : 0.0f;
    __syncthreads();

    long long base = (long long)(blockIdx.x * blockDim.x + threadIdx.x) * CHUNK;
    if (base >= n_atoms) return;

    if (base + CHUNK <= n_atoms) {
        // One 4-atom chunk per thread: 2 LDG.128, 4 LDS, short run loop.
        // CTA retires quickly; GigaThread backfill keeps SMs full of warps
        // that are in their load phase.
        int4 zv = *reinterpret_cast<const int4*>(zs + base);
        int4 sv = *reinterpret_cast<const int4*>(seg + base);

        int   s[4] = {sv.x, sv.y, sv.z, sv.w};
        int   z[4] = {zv.x, zv.y, zv.z, zv.w};

        int cur_seg = s[0];
        float run_sum = 0.0f;
#pragma unroll
        for (int k = 0; k < 4; k++) {
            if (s[k] != cur_seg) {
                atomicAdd(out + cur_seg, run_sum);   // interior run boundary
                cur_seg = s[k];
                run_sum = 0.0f;
            }
            run_sum += s_se[z[k]];
        }
        atomicAdd(out + cur_seg, run_sum);           // trailing run
    } else {
        // Tail safety (not hit for 8388608 atoms, but be general)
        int cs = -1; float rs = 0.0f;
        for (long long i = base; i < n_atoms; i++) {
            int s = seg[i];
            if (s != cs) { if (cs >= 0) atomicAdd(out + cs, rs); cs = s; rs = 0.0f; }
            rs += s_se[zs[i]];
        }
        if (cs >= 0) atomicAdd(out + cs, rs);
    }
}

extern "C" void kernel_launch(void* const* d_in, const int* in_sizes, int n_in,
                              void* d_out, int out_size) {
    const float* energy = (const float*)d_in[0];
    const int*   zs     = (const int*)d_in[1];
    const int*   seg    = (const int*)d_in[2];
    const float* se     = (const float*)d_in[3];
    float* out = (float*)d_out;

    int n_mol   = in_sizes[0];
    int n_atoms = in_sizes[1];
    int n_se    = in_sizes[3];

    // 1) out = energy_readout (d_out comes in poisoned). n_mol is 4-aligned.
    {
        int n4 = n_mol / 4;
        int blocks = (n4 + TPB - 1) / TPB;
        init_out_kernel<<<blocks, TPB>>>(energy, out, n4);
    }

    // 2) one-4-atom-chunk-per-thread segment sum with run-compressed atomics
    {
        long long threads_needed = ((long long)n_atoms + CHUNK - 1) / CHUNK;
        int blocks = (int)((threads_needed + TPB - 1) / TPB);
        self_energy_segsum_kernel<<<blocks, TPB>>>(zs, seg, se, out, n_atoms, n_se);
    }
}

// round 14
// speedup vs baseline: 1.1555x; 1.1555x over previous
#include <cuda_runtime.h>
#include <cuda_bf16.h>

// Inputs (metadata order):
//   d_in[0] : energy_readout            float32 [262144]
//   d_in[1] : atomic_numbers            int32   [8388608]
//   d_in[2] : atomic_subsystem_indices  int32   [8388608]  (sorted ascending)
//   d_in[3] : self_energies_tensor      float32 [100]
// Output: float32 [262144] = energy_readout + segment_sum(se[Z], seg_idx)

#define CHUNK 8           // atoms per thread (exactly one chunk per thread)
#define TPB 128

__global__ void init_out_kernel(const float* __restrict__ e,
                                float* __restrict__ out, int n4) {
    int i = blockIdx.x * blockDim.x + threadIdx.x;
    if (i < n4) {
        reinterpret_cast<float4*>(out)[i] =
            reinterpret_cast<const float4*>(e)[i];
    }
}

__global__ void __launch_bounds__(TPB, 16)
self_energy_segsum_kernel(const int* __restrict__ zs,
                          const int* __restrict__ seg,
                          const float* __restrict__ se,
                          float* __restrict__ out,
                          int n_atoms) {
    // No smem LUT, no prologue barrier: se is 400B = 7 cache lines, resident
    // in L1 after first touch (L1 persists within a launch). Threads issue
    // their streaming loads immediately on CTA start.
    long long base = (long long)(blockIdx.x * blockDim.x + threadIdx.x) * CHUNK;
    if (base >= n_atoms) return;

    if (base + CHUNK <= n_atoms) {
        const int4* z4 = reinterpret_cast<const int4*>(zs + base);
        const int4* s4 = reinterpret_cast<const int4*>(seg + base);

        int4 zv0 = z4[0], zv1 = z4[1];   // front-batched (MLP=4)
        int4 sv0 = s4[0], sv1 = s4[1];

        // LUT gathers from L1-resident table.
        float e0 = __ldg(se + zv0.x), e1 = __ldg(se + zv0.y);
        float e2 = __ldg(se + zv0.z), e3 = __ldg(se + zv0.w);
        float e4 = __ldg(se + zv1.x), e5 = __ldg(se + zv1.y);
        float e6 = __ldg(se + zv1.z), e7 = __ldg(se + zv1.w);

        int   s[8] = {sv0.x, sv0.y, sv0.z, sv0.w, sv1.x, sv1.y, sv1.z, sv1.w};
        float e[8] = {e0, e1, e2, e3, e4, e5, e6, e7};

        int cur_seg = s[0];
        float run_sum = 0.0f;
#pragma unroll
        for (int k = 0; k < 8; k++) {
            if (s[k] != cur_seg) {
                atomicAdd(out + cur_seg, run_sum);   // interior run boundary
                cur_seg = s[k];
                run_sum = 0.0f;
            }
            run_sum += e[k];
        }
        atomicAdd(out + cur_seg, run_sum);           // trailing run
    } else {
        // Tail safety (not hit for 8388608 atoms, but be general)
        int cs = -1; float rs = 0.0f;
        for (long long i = base; i < n_atoms; i++) {
            int s = seg[i];
            if (s != cs) { if (cs >= 0) atomicAdd(out + cs, rs); cs = s; rs = 0.0f; }
            rs += __ldg(se + zs[i]);
        }
        if (cs >= 0) atomicAdd(out + cs, rs);
    }
}

extern "C" void kernel_launch(void* const* d_in, const int* in_sizes, int n_in,
                              void* d_out, int out_size) {
    const float* energy = (const float*)d_in[0];
    const int*   zs     = (const int*)d_in[1];
    const int*   seg    = (const int*)d_in[2];
    const float* se     = (const float*)d_in[3];
    float* out = (float*)d_out;

    int n_mol   = in_sizes[0];
    int n_atoms = in_sizes[1];

    // 1) out = energy_readout (d_out comes in poisoned). n_mol is 4-aligned.
    {
        int n4 = n_mol / 4;
        int blocks = (n4 + TPB - 1) / TPB;
        init_out_kernel<<<blocks, TPB>>>(energy, out, n4);
    }

    // 2) one-chunk-per-thread segment sum, LUT served from L1
    {
        long long threads_needed = ((long long)n_atoms + CHUNK - 1) / CHUNK;
        int blocks = (int)((threads_needed + TPB - 1) / TPB);
        self_energy_segsum_kernel<<<blocks, TPB>>>(zs, seg, se, out, n_atoms);
    }
}